// round 15
// baseline (speedup 1.0000x reference)
#include <cuda_runtime.h>
#include <cuda_fp16.h>
#include <cstdint>

#define N_NODES   100000
#define N_EDGES   1600000
#define IN_FEATS  256
#define OUT_FEATS 128
#define BIN_CAP   128                   // fixed slots per node (mean deg = 16)

// ---------------------------------------------------------------------------
// Scratch (__device__ globals; allocation in kernel_launch is forbidden)
// ---------------------------------------------------------------------------
__device__ __half g_hself_h[(size_t)N_NODES * OUT_FEATS];  // h_self fp16 (25.6 MB)
__device__ __half g_Whk[(size_t)OUT_FEATS * IN_FEATS];     // W^T half, [n][k]
__device__ int    g_idx_is64;
__device__ int    g_cnt[N_NODES];
__device__ int    g_ssrc[(size_t)N_NODES * BIN_CAP];

// ---------------------------------------------------------------------------
// Side stream + events (created once at load; not device-memory allocation)
// ---------------------------------------------------------------------------
struct StreamHolder {
    cudaStream_t s = nullptr;
    cudaEvent_t fork = nullptr, csr = nullptr;
    bool ok = false;
    StreamHolder() {
        if (cudaStreamCreateWithFlags(&s, cudaStreamNonBlocking) != cudaSuccess) return;
        if (cudaEventCreateWithFlags(&fork, cudaEventDisableTiming) != cudaSuccess) return;
        if (cudaEventCreateWithFlags(&csr,  cudaEventDisableTiming) != cudaSuccess) return;
        ok = true;
    }
};
static StreamHolder g_sh;

// ---------------------------------------------------------------------------
// Kernel 0: fused index-dtype detect (block 0) + zero g_cnt (blocks 1..)
// ---------------------------------------------------------------------------
__global__ void detect_zero_kernel(const void* dst_raw, int n_elems) {
    if (blockIdx.x == 0) {
        __shared__ int bad;
        if (threadIdx.x == 0) bad = 0;
        __syncthreads();
        const long long* p = (const long long*)dst_raw;
        const int samples = 4096;
        for (int i = threadIdx.x; i < samples; i += blockDim.x) {
            int idx = (int)(((long long)i * (n_elems / 2 - 1)) / (samples - 1));
            long long v = p[idx];
            if (v < 0 || v >= N_NODES) atomicExch(&bad, 1);
        }
        __syncthreads();
        if (threadIdx.x == 0) g_idx_is64 = bad ? 0 : 1;
    } else {
        int i = (blockIdx.x - 1) * blockDim.x + threadIdx.x;
        if (i < N_NODES) g_cnt[i] = 0;
    }
}

// ---------------------------------------------------------------------------
// Direct binning (round-11 proven): one pass, 4 edges/thread.
// ---------------------------------------------------------------------------
__global__ void bin_kernel(const void* __restrict__ src_raw,
                           const void* __restrict__ dst_raw) {
    const int base = (blockIdx.x * blockDim.x + threadIdx.x) * 4;
    if (base >= N_EDGES) return;
    const int lim = N_EDGES - base >= 4 ? 4 : N_EDGES - base;
    int s[4], d[4];
    if (g_idx_is64) {
        const long long* ps = (const long long*)src_raw;
        const long long* pd = (const long long*)dst_raw;
        #pragma unroll
        for (int j = 0; j < 4; j++) {
            s[j] = (j < lim) ? (int)__ldg(&ps[base + j]) : -1;
            d[j] = (j < lim) ? (int)__ldg(&pd[base + j]) : -1;
        }
    } else {
        const int* ps = (const int*)src_raw;
        const int* pd = (const int*)dst_raw;
        #pragma unroll
        for (int j = 0; j < 4; j++) {
            s[j] = (j < lim) ? __ldg(&ps[base + j]) : -1;
            d[j] = (j < lim) ? __ldg(&pd[base + j]) : -1;
        }
    }
    #pragma unroll
    for (int j = 0; j < 4; j++) {
        if ((unsigned)s[j] < N_NODES && (unsigned)d[j] < N_NODES) {
            const int pos = atomicAdd(&g_cnt[d[j]], 1);
            if (pos < BIN_CAP)
                g_ssrc[(size_t)d[j] * BIN_CAP + pos] = s[j];
        }
    }
}

// ---------------------------------------------------------------------------
// W pre-convert: g_Whk[n][k] = half(W[k][n])
// ---------------------------------------------------------------------------
__global__ void wh_kernel(const float* __restrict__ W) {
    int i = blockIdx.x * blockDim.x + threadIdx.x;
    if (i >= IN_FEATS * OUT_FEATS) return;
    int n = i & (OUT_FEATS - 1);
    int k = i >> 7;
    g_Whk[(size_t)n * IN_FEATS + k] = __float2half(W[(size_t)k * OUT_FEATS + n]);
}

// ---------------------------------------------------------------------------
// GEMM: fp16 m16n8k16, fp32 accumulate, 2-stage cp.async pipeline.
// CTA tile 64x128 (M-split), 8 warps in 2x4 grid, warp tile 32x32,
// 3 CTAs/SM (reg cap 85, smem 76.8 KB total for 2 stages x 38.4 KB).
// ---------------------------------------------------------------------------
#define BK 32
#define CTAM 64
#define ASTR 36
#define BSTRH 40
#define ABUF  (CTAM * ASTR)             // floats per A stage (2304)
#define BBUFH (128 * BSTRH)             // halves per B stage (5120)
#define SMEM_BYTES (2 * ABUF * 4 + 2 * BBUFH * 2)   // 18432 + 20480 = 38912... (x2 stages inline)

__device__ __forceinline__ void mma_fp16(float* d, const uint32_t* a,
                                         uint32_t b0, uint32_t b1) {
    asm volatile(
        "mma.sync.aligned.m16n8k16.row.col.f32.f16.f16.f32 "
        "{%0,%1,%2,%3}, {%4,%5,%6,%7}, {%8,%9}, {%0,%1,%2,%3};"
        : "+f"(d[0]), "+f"(d[1]), "+f"(d[2]), "+f"(d[3])
        : "r"(a[0]), "r"(a[1]), "r"(a[2]), "r"(a[3]), "r"(b0), "r"(b1));
}

__device__ __forceinline__ uint32_t pack_h2(float2 p) {
    __half2 h = __floats2half2_rn(p.x, p.y);
    return *reinterpret_cast<uint32_t*>(&h);
}

__device__ __forceinline__ void cp16(void* smem_dst, const void* gsrc) {
    uint32_t sa;
    asm("{ .reg .u64 t; cvta.to.shared.u64 t, %1; cvt.u32.u64 %0, t; }"
        : "=r"(sa) : "l"(smem_dst));
    asm volatile("cp.async.ca.shared.global [%0], [%1], 16;"
                 :: "r"(sa), "l"(gsrc) : "memory");
}

__global__ __launch_bounds__(256, 3)
void gemm_fp16_kernel(const float* __restrict__ feat) {
    extern __shared__ float smem[];
    float*  As = smem;                                        // [2][64][ASTR]
    __half* Bs = reinterpret_cast<__half*>(smem + 2 * ABUF);  // [2][128][BSTRH]

    const int tid  = threadIdx.x;
    const int lane = tid & 31;
    const int warp = tid >> 5;
    const int m0   = blockIdx.x * CTAM;

    const int wm = (warp >> 2) * 32;    // 0 or 32
    const int wn = (warp & 3) * 32;     // 0,32,64,96
    const int g  = lane >> 2;
    const int c  = lane & 3;

    float acc[2][4][4];
    #pragma unroll
    for (int i = 0; i < 2; i++)
        #pragma unroll
        for (int j = 0; j < 4; j++)
            #pragma unroll
            for (int q = 0; q < 4; q++) acc[i][j][q] = 0.f;

    // tile 0 loads: A = 64 rows x 32 k floats = 512 float4 (2/thread);
    //               B = 128 n x 32 k halves = 512 x 16B (2/thread)
    #pragma unroll
    for (int p = 0; p < 2; p++) {
        const int ch = tid + 256 * p;
        int row = m0 + (ch >> 3);
        row = row < N_NODES ? row : N_NODES - 1;
        const int q = (ch & 7) * 4;
        cp16(&As[(ch >> 3) * ASTR + q], feat + (size_t)row * IN_FEATS + q);
    }
    #pragma unroll
    for (int p = 0; p < 2; p++) {
        const int ch = tid + 256 * p;
        const int n  = ch >> 2;
        const int ko = (ch & 3) * 8;
        cp16(&Bs[n * BSTRH + ko], g_Whk + (size_t)n * IN_FEATS + ko);
    }
    asm volatile("cp.async.commit_group;" ::: "memory");

    int buf = 0;
    for (int kt = 0; kt < IN_FEATS / BK; kt++) {
        if (kt + 1 < IN_FEATS / BK) {
            const int k0 = (kt + 1) * BK;
            float*  Ad = As + (buf ^ 1) * ABUF;
            __half* Bd = Bs + (buf ^ 1) * BBUFH;
            #pragma unroll
            for (int p = 0; p < 2; p++) {
                const int ch = tid + 256 * p;
                int row = m0 + (ch >> 3);
                row = row < N_NODES ? row : N_NODES - 1;
                const int q = (ch & 7) * 4;
                cp16(&Ad[(ch >> 3) * ASTR + q],
                     feat + (size_t)row * IN_FEATS + k0 + q);
            }
            #pragma unroll
            for (int p = 0; p < 2; p++) {
                const int ch = tid + 256 * p;
                const int n  = ch >> 2;
                const int ko = (ch & 3) * 8;
                cp16(&Bd[n * BSTRH + ko],
                     g_Whk + (size_t)n * IN_FEATS + k0 + ko);
            }
            asm volatile("cp.async.commit_group;" ::: "memory");
            asm volatile("cp.async.wait_group 1;" ::: "memory");
        } else {
            asm volatile("cp.async.wait_group 0;" ::: "memory");
        }
        __syncthreads();

        const float*  Ab = As + buf * ABUF;
        const __half* Bb = Bs + buf * BBUFH;

        #pragma unroll
        for (int s = 0; s < 2; s++) {
            const int kb = s * 16;
            uint32_t a[2][4];
            #pragma unroll
            for (int i = 0; i < 2; i++) {
                const int r = wm + i * 16 + g;
                a[i][0] = pack_h2(*reinterpret_cast<const float2*>(
                    &Ab[r * ASTR + kb + 2 * c]));
                a[i][1] = pack_h2(*reinterpret_cast<const float2*>(
                    &Ab[(r + 8) * ASTR + kb + 2 * c]));
                a[i][2] = pack_h2(*reinterpret_cast<const float2*>(
                    &Ab[r * ASTR + kb + 2 * c + 8]));
                a[i][3] = pack_h2(*reinterpret_cast<const float2*>(
                    &Ab[(r + 8) * ASTR + kb + 2 * c + 8]));
            }
            #pragma unroll
            for (int j = 0; j < 4; j++) {
                const int n = wn + j * 8 + g;
                const uint32_t b0 = *reinterpret_cast<const uint32_t*>(
                    &Bb[n * BSTRH + kb + 2 * c]);
                const uint32_t b1 = *reinterpret_cast<const uint32_t*>(
                    &Bb[n * BSTRH + kb + 2 * c + 8]);
                mma_fp16(acc[0][j], a[0], b0, b1);
                mma_fp16(acc[1][j], a[1], b0, b1);
            }
        }
        __syncthreads();
        buf ^= 1;
    }

    // epilogue: pack fp32 accumulators to half2 and store
    #pragma unroll
    for (int i = 0; i < 2; i++) {
        #pragma unroll
        for (int j = 0; j < 4; j++) {
            const int row0 = m0 + wm + i * 16 + g;
            const int col  = wn + j * 8 + 2 * c;
            if (row0 < N_NODES) {
                __half2 h = __floats2half2_rn(acc[i][j][0], acc[i][j][1]);
                *reinterpret_cast<__half2*>(
                    g_hself_h + (size_t)row0 * OUT_FEATS + col) = h;
            }
            const int row1 = row0 + 8;
            if (row1 < N_NODES) {
                __half2 h = __floats2half2_rn(acc[i][j][2], acc[i][j][3]);
                *reinterpret_cast<__half2*>(
                    g_hself_h + (size_t)row1 * OUT_FEATS + col) = h;
            }
        }
    }
}

// ---------------------------------------------------------------------------
// Aggregate + finalize (round-12/14 proven): one warp per node,
// 8-way unrolled gather loop, fp32 accumulation over fp16 rows.
// ---------------------------------------------------------------------------
__global__ __launch_bounds__(256)
void aggregate_kernel(float* __restrict__ out) {
    const int n = (int)((blockIdx.x * (unsigned)blockDim.x + threadIdx.x) >> 5);
    if (n >= N_NODES) return;
    const int lane = threadIdx.x & 31;

    int cnt = g_cnt[n];
    cnt = cnt < BIN_CAP ? cnt : BIN_CAP;
    const int beg = n * BIN_CAP;
    const int end = beg + cnt;

    const int lofs = lane * 4;   // halves

    float4 acc = make_float4(0.f, 0.f, 0.f, 0.f);

    int i = beg;
    for (; i + 8 <= end; i += 8) {
        int sv[8];
        #pragma unroll
        for (int q = 0; q < 8; q++) sv[q] = __ldg(&g_ssrc[i + q]);
        uint2 u[8];
        #pragma unroll
        for (int q = 0; q < 8; q++)
            u[q] = __ldg(reinterpret_cast<const uint2*>(
                g_hself_h + (size_t)sv[q] * OUT_FEATS + lofs));
        #pragma unroll
        for (int q = 0; q < 8; q++) {
            const float2 lo = __half22float2(*reinterpret_cast<const __half2*>(&u[q].x));
            const float2 hi = __half22float2(*reinterpret_cast<const __half2*>(&u[q].y));
            acc.x += lo.x; acc.y += lo.y; acc.z += hi.x; acc.w += hi.y;
        }
    }
    for (; i + 4 <= end; i += 4) {
        int sv[4];
        #pragma unroll
        for (int q = 0; q < 4; q++) sv[q] = __ldg(&g_ssrc[i + q]);
        uint2 u[4];
        #pragma unroll
        for (int q = 0; q < 4; q++)
            u[q] = __ldg(reinterpret_cast<const uint2*>(
                g_hself_h + (size_t)sv[q] * OUT_FEATS + lofs));
        #pragma unroll
        for (int q = 0; q < 4; q++) {
            const float2 lo = __half22float2(*reinterpret_cast<const __half2*>(&u[q].x));
            const float2 hi = __half22float2(*reinterpret_cast<const __half2*>(&u[q].y));
            acc.x += lo.x; acc.y += lo.y; acc.z += hi.x; acc.w += hi.y;
        }
    }
    for (; i < end; i++) {
        const int s0 = __ldg(&g_ssrc[i]);
        const uint2 u = __ldg(reinterpret_cast<const uint2*>(
            g_hself_h + (size_t)s0 * OUT_FEATS + lofs));
        const float2 lo = __half22float2(*reinterpret_cast<const __half2*>(&u.x));
        const float2 hi = __half22float2(*reinterpret_cast<const __half2*>(&u.y));
        acc.x += lo.x; acc.y += lo.y; acc.z += hi.x; acc.w += hi.y;
    }

    const uint2 uh = __ldg(reinterpret_cast<const uint2*>(
        g_hself_h + (size_t)n * OUT_FEATS + lofs));
    const float2 hlo = __half22float2(*reinterpret_cast<const __half2*>(&uh.x));
    const float2 hhi = __half22float2(*reinterpret_cast<const __half2*>(&uh.y));

    const float invd = 1.0f / ((float)cnt + 1.0f);

    float4 r;
    r.x = fmaxf((acc.x + hlo.x) * invd, 0.f);
    r.y = fmaxf((acc.y + hlo.y) * invd, 0.f);
    r.z = fmaxf((acc.z + hhi.x) * invd, 0.f);
    r.w = fmaxf((acc.w + hhi.y) * invd, 0.f);

    *reinterpret_cast<float4*>(out + (size_t)n * OUT_FEATS + lane * 4) = r;
}

// ---------------------------------------------------------------------------
// kernel_launch: side = detect+zero -> bin; main = wh -> gemm; join; aggregate.
// ---------------------------------------------------------------------------
extern "C" void kernel_launch(void* const* d_in, const int* in_sizes, int n_in,
                              void* d_out, int out_size) {
    const float* feat = (const float*)d_in[0];
    const float* W    = (const float*)d_in[1];
    const void*  src  = d_in[2];
    const void*  dst  = d_in[3];
    float*       out  = (float*)d_out;

    cudaFuncSetAttribute(gemm_fp16_kernel,
                         cudaFuncAttributeMaxDynamicSharedMemorySize, SMEM_BYTES);

    const int gemm_blocks = (N_NODES + CTAM - 1) / CTAM;    // 1563
    const int agg_blocks  = (int)(((long long)N_NODES * 32 + 255) / 256);
    const int dz_blocks   = 1 + (N_NODES + 255) / 256;

    if (g_sh.ok) {
        cudaEventRecord(g_sh.fork, 0);
        cudaStreamWaitEvent(g_sh.s, g_sh.fork, 0);

        // binning chain on side stream
        detect_zero_kernel<<<dz_blocks, 256, 0, g_sh.s>>>(dst, in_sizes[3]);
        bin_kernel<<<(N_EDGES / 4 + 255) / 256, 256, 0, g_sh.s>>>(src, dst);
        cudaEventRecord(g_sh.csr, g_sh.s);

        // GEMM chain on default stream
        wh_kernel<<<(IN_FEATS * OUT_FEATS + 255) / 256, 256>>>(W);
        gemm_fp16_kernel<<<gemm_blocks, 256, SMEM_BYTES>>>(feat);

        // join, then aggregate
        cudaStreamWaitEvent(0, g_sh.csr, 0);
        aggregate_kernel<<<agg_blocks, 256>>>(out);
    } else {
        detect_zero_kernel<<<dz_blocks, 256>>>(dst, in_sizes[3]);
        wh_kernel<<<(IN_FEATS * OUT_FEATS + 255) / 256, 256>>>(W);
        gemm_fp16_kernel<<<gemm_blocks, 256, SMEM_BYTES>>>(feat);
        bin_kernel<<<(N_EDGES / 4 + 255) / 256, 256>>>(src, dst);
        aggregate_kernel<<<agg_blocks, 256>>>(out);
    }
}

// round 16
// speedup vs baseline: 1.0241x; 1.0241x over previous
#include <cuda_runtime.h>
#include <cuda_fp16.h>
#include <cstdint>

#define N_NODES   100000
#define N_EDGES   1600000
#define IN_FEATS  256
#define OUT_FEATS 128
#define BIN_CAP   128                   // fixed slots per node (mean deg = 16)

// ---------------------------------------------------------------------------
// Scratch (__device__ globals; allocation in kernel_launch is forbidden)
// ---------------------------------------------------------------------------
__device__ __half g_hself_h[(size_t)N_NODES * OUT_FEATS];  // h_self fp16 (25.6 MB)
__device__ __half g_Whk[(size_t)OUT_FEATS * IN_FEATS];     // W^T half, [n][k]
__device__ int    g_idx_is64;
__device__ int    g_cnt[N_NODES];
__device__ int    g_ssrc[(size_t)N_NODES * BIN_CAP];

// ---------------------------------------------------------------------------
// Side stream + events (created once at load; not device-memory allocation)
// ---------------------------------------------------------------------------
struct StreamHolder {
    cudaStream_t s = nullptr;
    cudaEvent_t fork = nullptr, csr = nullptr;
    bool ok = false;
    StreamHolder() {
        if (cudaStreamCreateWithFlags(&s, cudaStreamNonBlocking) != cudaSuccess) return;
        if (cudaEventCreateWithFlags(&fork, cudaEventDisableTiming) != cudaSuccess) return;
        if (cudaEventCreateWithFlags(&csr,  cudaEventDisableTiming) != cudaSuccess) return;
        ok = true;
    }
};
static StreamHolder g_sh;

// ---------------------------------------------------------------------------
// Kernel 0: fused index-dtype detect (block 0) + zero g_cnt (blocks 1..)
// ---------------------------------------------------------------------------
__global__ void detect_zero_kernel(const void* dst_raw, int n_elems) {
    if (blockIdx.x == 0) {
        __shared__ int bad;
        if (threadIdx.x == 0) bad = 0;
        __syncthreads();
        const long long* p = (const long long*)dst_raw;
        const int samples = 4096;
        for (int i = threadIdx.x; i < samples; i += blockDim.x) {
            int idx = (int)(((long long)i * (n_elems / 2 - 1)) / (samples - 1));
            long long v = p[idx];
            if (v < 0 || v >= N_NODES) atomicExch(&bad, 1);
        }
        __syncthreads();
        if (threadIdx.x == 0) g_idx_is64 = bad ? 0 : 1;
    } else {
        int i = (blockIdx.x - 1) * blockDim.x + threadIdx.x;
        if (i < N_NODES) g_cnt[i] = 0;
    }
}

// ---------------------------------------------------------------------------
// Direct binning (round-11 proven): one pass, 4 edges/thread.
// ---------------------------------------------------------------------------
__global__ void bin_kernel(const void* __restrict__ src_raw,
                           const void* __restrict__ dst_raw) {
    const int base = (blockIdx.x * blockDim.x + threadIdx.x) * 4;
    if (base >= N_EDGES) return;
    const int lim = N_EDGES - base >= 4 ? 4 : N_EDGES - base;
    int s[4], d[4];
    if (g_idx_is64) {
        const long long* ps = (const long long*)src_raw;
        const long long* pd = (const long long*)dst_raw;
        #pragma unroll
        for (int j = 0; j < 4; j++) {
            s[j] = (j < lim) ? (int)__ldg(&ps[base + j]) : -1;
            d[j] = (j < lim) ? (int)__ldg(&pd[base + j]) : -1;
        }
    } else {
        const int* ps = (const int*)src_raw;
        const int* pd = (const int*)dst_raw;
        #pragma unroll
        for (int j = 0; j < 4; j++) {
            s[j] = (j < lim) ? __ldg(&ps[base + j]) : -1;
            d[j] = (j < lim) ? __ldg(&pd[base + j]) : -1;
        }
    }
    #pragma unroll
    for (int j = 0; j < 4; j++) {
        if ((unsigned)s[j] < N_NODES && (unsigned)d[j] < N_NODES) {
            const int pos = atomicAdd(&g_cnt[d[j]], 1);
            if (pos < BIN_CAP)
                g_ssrc[(size_t)d[j] * BIN_CAP + pos] = s[j];
        }
    }
}

// ---------------------------------------------------------------------------
// W pre-convert: g_Whk[n][k] = half(W[k][n])
// ---------------------------------------------------------------------------
__global__ void wh_kernel(const float* __restrict__ W) {
    int i = blockIdx.x * blockDim.x + threadIdx.x;
    if (i >= IN_FEATS * OUT_FEATS) return;
    int n = i & (OUT_FEATS - 1);
    int k = i >> 7;
    g_Whk[(size_t)n * IN_FEATS + k] = __float2half(W[(size_t)k * OUT_FEATS + n]);
}

// ---------------------------------------------------------------------------
// GEMM: fp16 m16n8k16, fp32 accumulate. R14 tile shape (CTA 128x128, 8 warps
// 4x2, warp tile 32x64) with a CORRECT 3-stage cp.async pipeline:
// refill is issued BEFORE the wait (R12 ordering), target stage was freed by
// the end-of-previous-iteration barrier. cp.async.cg bypasses L1.
// ---------------------------------------------------------------------------
#define BK 32
#define NKT (IN_FEATS / BK)             // 8
#define ASTR 36
#define BSTRH 40
#define ABUF  (128 * ASTR)              // floats per A stage
#define BBUFH (128 * BSTRH)             // halves per B stage
#define STAGE_BYTES (ABUF * 4 + BBUFH * 2)          // 28672
#define SMEM_BYTES  (3 * STAGE_BYTES)               // 86016

__device__ __forceinline__ void mma_fp16(float* d, const uint32_t* a,
                                         uint32_t b0, uint32_t b1) {
    asm volatile(
        "mma.sync.aligned.m16n8k16.row.col.f32.f16.f16.f32 "
        "{%0,%1,%2,%3}, {%4,%5,%6,%7}, {%8,%9}, {%0,%1,%2,%3};"
        : "+f"(d[0]), "+f"(d[1]), "+f"(d[2]), "+f"(d[3])
        : "r"(a[0]), "r"(a[1]), "r"(a[2]), "r"(a[3]), "r"(b0), "r"(b1));
}

__device__ __forceinline__ uint32_t pack_h2(float2 p) {
    __half2 h = __floats2half2_rn(p.x, p.y);
    return *reinterpret_cast<uint32_t*>(&h);
}

__device__ __forceinline__ void cp16(void* smem_dst, const void* gsrc) {
    uint32_t sa;
    asm("{ .reg .u64 t; cvta.to.shared.u64 t, %1; cvt.u32.u64 %0, t; }"
        : "=r"(sa) : "l"(smem_dst));
    asm volatile("cp.async.cg.shared.global [%0], [%1], 16;"
                 :: "r"(sa), "l"(gsrc) : "memory");
}

__global__ __launch_bounds__(256, 2)
void gemm_fp16_kernel(const float* __restrict__ feat) {
    extern __shared__ char smem_raw[];

    const int tid  = threadIdx.x;
    const int lane = tid & 31;
    const int warp = tid >> 5;
    const int m0   = blockIdx.x * 128;

    const int wm = (warp >> 1) * 32;
    const int wn = (warp & 1) * 64;
    const int g  = lane >> 2;
    const int c  = lane & 3;

    float acc[2][8][4];
    #pragma unroll
    for (int i = 0; i < 2; i++)
        #pragma unroll
        for (int j = 0; j < 8; j++)
            #pragma unroll
            for (int q = 0; q < 4; q++) acc[i][j][q] = 0.f;

    float*  Asg[3];
    __half* Bsg[3];
    #pragma unroll
    for (int st = 0; st < 3; st++) {
        char* base = smem_raw + st * STAGE_BYTES;
        Asg[st] = reinterpret_cast<float*>(base);
        Bsg[st] = reinterpret_cast<__half*>(base + ABUF * 4);
    }

    auto issue = [&](int kt, int st) {
        const int k0 = kt * BK;
        float*  Ad = Asg[st];
        __half* Bd = Bsg[st];
        #pragma unroll
        for (int p = 0; p < 4; p++) {       // A: 128 rows x 32 k floats
            const int ch = tid + 256 * p;
            int row = m0 + (ch >> 3);
            row = row < N_NODES ? row : N_NODES - 1;
            const int q = (ch & 7) * 4;
            cp16(&Ad[(ch >> 3) * ASTR + q], feat + (size_t)row * IN_FEATS + k0 + q);
        }
        #pragma unroll
        for (int p = 0; p < 2; p++) {       // B: 128 n x 32 k halves
            const int ch = tid + 256 * p;
            const int n  = ch >> 2;
            const int ko = (ch & 3) * 8;
            cp16(&Bd[n * BSTRH + ko], g_Whk + (size_t)n * IN_FEATS + k0 + ko);
        }
        asm volatile("cp.async.commit_group;" ::: "memory");
    };

    // prologue: two stages in flight
    issue(0, 0);
    issue(1, 1);

    for (int kt = 0; kt < NKT; kt++) {
        // refill FIRST (R12 ordering): stage (kt+2)%3 was freed by the
        // end-of-iteration barrier of kt-1. Then wait for tile kt.
        if (kt + 2 < NKT) {
            issue(kt + 2, (kt + 2) % 3);
            asm volatile("cp.async.wait_group 2;" ::: "memory");
        } else if (kt + 1 < NKT) {
            asm volatile("cp.async.wait_group 1;" ::: "memory");
        } else {
            asm volatile("cp.async.wait_group 0;" ::: "memory");
        }
        __syncthreads();

        const float*  Ab = Asg[kt % 3];
        const __half* Bb = Bsg[kt % 3];

        #pragma unroll
        for (int s = 0; s < 2; s++) {
            const int kb = s * 16;
            uint32_t a[2][4];
            #pragma unroll
            for (int i = 0; i < 2; i++) {
                const int r = wm + i * 16 + g;
                a[i][0] = pack_h2(*reinterpret_cast<const float2*>(
                    &Ab[r * ASTR + kb + 2 * c]));
                a[i][1] = pack_h2(*reinterpret_cast<const float2*>(
                    &Ab[(r + 8) * ASTR + kb + 2 * c]));
                a[i][2] = pack_h2(*reinterpret_cast<const float2*>(
                    &Ab[r * ASTR + kb + 2 * c + 8]));
                a[i][3] = pack_h2(*reinterpret_cast<const float2*>(
                    &Ab[(r + 8) * ASTR + kb + 2 * c + 8]));
            }
            #pragma unroll
            for (int j = 0; j < 8; j++) {
                const int n = wn + j * 8 + g;
                const uint32_t b0 = *reinterpret_cast<const uint32_t*>(
                    &Bb[n * BSTRH + kb + 2 * c]);
                const uint32_t b1 = *reinterpret_cast<const uint32_t*>(
                    &Bb[n * BSTRH + kb + 2 * c + 8]);
                mma_fp16(acc[0][j], a[0], b0, b1);
                mma_fp16(acc[1][j], a[1], b0, b1);
            }
        }
        __syncthreads();   // frees stage kt%3 for the refill in iteration kt+1
    }

    // epilogue: pack fp32 accumulators to half2 and store
    #pragma unroll
    for (int i = 0; i < 2; i++) {
        #pragma unroll
        for (int j = 0; j < 8; j++) {
            const int row0 = m0 + wm + i * 16 + g;
            const int col  = wn + j * 8 + 2 * c;
            if (row0 < N_NODES) {
                __half2 h = __floats2half2_rn(acc[i][j][0], acc[i][j][1]);
                *reinterpret_cast<__half2*>(
                    g_hself_h + (size_t)row0 * OUT_FEATS + col) = h;
            }
            const int row1 = row0 + 8;
            if (row1 < N_NODES) {
                __half2 h = __floats2half2_rn(acc[i][j][2], acc[i][j][3]);
                *reinterpret_cast<__half2*>(
                    g_hself_h + (size_t)row1 * OUT_FEATS + col) = h;
            }
        }
    }
}

// ---------------------------------------------------------------------------
// Aggregate + finalize (round-12/14 proven): one warp per node,
// 8-way unrolled gather loop, fp32 accumulation over fp16 rows.
// ---------------------------------------------------------------------------
__global__ __launch_bounds__(256)
void aggregate_kernel(float* __restrict__ out) {
    const int n = (int)((blockIdx.x * (unsigned)blockDim.x + threadIdx.x) >> 5);
    if (n >= N_NODES) return;
    const int lane = threadIdx.x & 31;

    int cnt = g_cnt[n];
    cnt = cnt < BIN_CAP ? cnt : BIN_CAP;
    const int beg = n * BIN_CAP;
    const int end = beg + cnt;

    const int lofs = lane * 4;   // halves

    float4 acc = make_float4(0.f, 0.f, 0.f, 0.f);

    int i = beg;
    for (; i + 8 <= end; i += 8) {
        int sv[8];
        #pragma unroll
        for (int q = 0; q < 8; q++) sv[q] = __ldg(&g_ssrc[i + q]);
        uint2 u[8];
        #pragma unroll
        for (int q = 0; q < 8; q++)
            u[q] = __ldg(reinterpret_cast<const uint2*>(
                g_hself_h + (size_t)sv[q] * OUT_FEATS + lofs));
        #pragma unroll
        for (int q = 0; q < 8; q++) {
            const float2 lo = __half22float2(*reinterpret_cast<const __half2*>(&u[q].x));
            const float2 hi = __half22float2(*reinterpret_cast<const __half2*>(&u[q].y));
            acc.x += lo.x; acc.y += lo.y; acc.z += hi.x; acc.w += hi.y;
        }
    }
    for (; i + 4 <= end; i += 4) {
        int sv[4];
        #pragma unroll
        for (int q = 0; q < 4; q++) sv[q] = __ldg(&g_ssrc[i + q]);
        uint2 u[4];
        #pragma unroll
        for (int q = 0; q < 4; q++)
            u[q] = __ldg(reinterpret_cast<const uint2*>(
                g_hself_h + (size_t)sv[q] * OUT_FEATS + lofs));
        #pragma unroll
        for (int q = 0; q < 4; q++) {
            const float2 lo = __half22float2(*reinterpret_cast<const __half2*>(&u[q].x));
            const float2 hi = __half22float2(*reinterpret_cast<const __half2*>(&u[q].y));
            acc.x += lo.x; acc.y += lo.y; acc.z += hi.x; acc.w += hi.y;
        }
    }
    for (; i < end; i++) {
        const int s0 = __ldg(&g_ssrc[i]);
        const uint2 u = __ldg(reinterpret_cast<const uint2*>(
            g_hself_h + (size_t)s0 * OUT_FEATS + lofs));
        const float2 lo = __half22float2(*reinterpret_cast<const __half2*>(&u.x));
        const float2 hi = __half22float2(*reinterpret_cast<const __half2*>(&u.y));
        acc.x += lo.x; acc.y += lo.y; acc.z += hi.x; acc.w += hi.y;
    }

    const uint2 uh = __ldg(reinterpret_cast<const uint2*>(
        g_hself_h + (size_t)n * OUT_FEATS + lofs));
    const float2 hlo = __half22float2(*reinterpret_cast<const __half2*>(&uh.x));
    const float2 hhi = __half22float2(*reinterpret_cast<const __half2*>(&uh.y));

    const float invd = 1.0f / ((float)cnt + 1.0f);

    float4 r;
    r.x = fmaxf((acc.x + hlo.x) * invd, 0.f);
    r.y = fmaxf((acc.y + hlo.y) * invd, 0.f);
    r.z = fmaxf((acc.z + hhi.x) * invd, 0.f);
    r.w = fmaxf((acc.w + hhi.y) * invd, 0.f);

    *reinterpret_cast<float4*>(out + (size_t)n * OUT_FEATS + lane * 4) = r;
}

// ---------------------------------------------------------------------------
// kernel_launch: side = detect+zero -> bin; main = wh -> gemm; join; aggregate.
// ---------------------------------------------------------------------------
extern "C" void kernel_launch(void* const* d_in, const int* in_sizes, int n_in,
                              void* d_out, int out_size) {
    const float* feat = (const float*)d_in[0];
    const float* W    = (const float*)d_in[1];
    const void*  src  = d_in[2];
    const void*  dst  = d_in[3];
    float*       out  = (float*)d_out;

    cudaFuncSetAttribute(gemm_fp16_kernel,
                         cudaFuncAttributeMaxDynamicSharedMemorySize, SMEM_BYTES);

    const int gemm_blocks = (N_NODES + 127) / 128;          // 782
    const int agg_blocks  = (int)(((long long)N_NODES * 32 + 255) / 256);
    const int dz_blocks   = 1 + (N_NODES + 255) / 256;

    if (g_sh.ok) {
        cudaEventRecord(g_sh.fork, 0);
        cudaStreamWaitEvent(g_sh.s, g_sh.fork, 0);

        // binning chain on side stream
        detect_zero_kernel<<<dz_blocks, 256, 0, g_sh.s>>>(dst, in_sizes[3]);
        bin_kernel<<<(N_EDGES / 4 + 255) / 256, 256, 0, g_sh.s>>>(src, dst);
        cudaEventRecord(g_sh.csr, g_sh.s);

        // GEMM chain on default stream
        wh_kernel<<<(IN_FEATS * OUT_FEATS + 255) / 256, 256>>>(W);
        gemm_fp16_kernel<<<gemm_blocks, 256, SMEM_BYTES>>>(feat);

        // join, then aggregate
        cudaStreamWaitEvent(0, g_sh.csr, 0);
        aggregate_kernel<<<agg_blocks, 256>>>(out);
    } else {
        detect_zero_kernel<<<dz_blocks, 256>>>(dst, in_sizes[3]);
        wh_kernel<<<(IN_FEATS * OUT_FEATS + 255) / 256, 256>>>(W);
        gemm_fp16_kernel<<<gemm_blocks, 256, SMEM_BYTES>>>(feat);
        bin_kernel<<<(N_EDGES / 4 + 255) / 256, 256>>>(src, dst);
        aggregate_kernel<<<agg_blocks, 256>>>(out);
    }
}

// round 17
// speedup vs baseline: 1.0967x; 1.0709x over previous
#include <cuda_runtime.h>
#include <cuda_fp16.h>
#include <cstdint>

#define N_NODES   100000
#define N_EDGES   1600000
#define IN_FEATS  256
#define OUT_FEATS 128
#define BIN_CAP   128                   // fixed slots per node (mean deg = 16)

// ---------------------------------------------------------------------------
// Scratch (__device__ globals; allocation in kernel_launch is forbidden)
// ---------------------------------------------------------------------------
__device__ __half g_hself_h[(size_t)N_NODES * OUT_FEATS];  // h_self fp16 (25.6 MB)
__device__ __half g_Whk[(size_t)OUT_FEATS * IN_FEATS];     // W^T half, [n][k]
__device__ int    g_idx_is64;
__device__ int    g_cnt[N_NODES];
__device__ int    g_ssrc[(size_t)N_NODES * BIN_CAP];

// ---------------------------------------------------------------------------
// Side stream + events (created once at load; not device-memory allocation)
// ---------------------------------------------------------------------------
struct StreamHolder {
    cudaStream_t s = nullptr;
    cudaEvent_t fork = nullptr, csr = nullptr, whdone = nullptr;
    bool ok = false;
    StreamHolder() {
        if (cudaStreamCreateWithFlags(&s, cudaStreamNonBlocking) != cudaSuccess) return;
        if (cudaEventCreateWithFlags(&fork, cudaEventDisableTiming) != cudaSuccess) return;
        if (cudaEventCreateWithFlags(&csr,  cudaEventDisableTiming) != cudaSuccess) return;
        if (cudaEventCreateWithFlags(&whdone, cudaEventDisableTiming) != cudaSuccess) return;
        ok = true;
    }
};
static StreamHolder g_sh;

// ---------------------------------------------------------------------------
// Kernel 0: fused index-dtype detect (block 0) + zero g_cnt (blocks 1..)
// ---------------------------------------------------------------------------
__global__ void detect_zero_kernel(const void* dst_raw, int n_elems) {
    if (blockIdx.x == 0) {
        __shared__ int bad;
        if (threadIdx.x == 0) bad = 0;
        __syncthreads();
        const long long* p = (const long long*)dst_raw;
        const int samples = 4096;
        for (int i = threadIdx.x; i < samples; i += blockDim.x) {
            int idx = (int)(((long long)i * (n_elems / 2 - 1)) / (samples - 1));
            long long v = p[idx];
            if (v < 0 || v >= N_NODES) atomicExch(&bad, 1);
        }
        __syncthreads();
        if (threadIdx.x == 0) g_idx_is64 = bad ? 0 : 1;
    } else {
        int i = (blockIdx.x - 1) * blockDim.x + threadIdx.x;
        if (i < N_NODES) g_cnt[i] = 0;
    }
}

// ---------------------------------------------------------------------------
// Direct binning (round-11 proven): one pass, 4 edges/thread.
// ---------------------------------------------------------------------------
__global__ void bin_kernel(const void* __restrict__ src_raw,
                           const void* __restrict__ dst_raw) {
    const int base = (blockIdx.x * blockDim.x + threadIdx.x) * 4;
    if (base >= N_EDGES) return;
    const int lim = N_EDGES - base >= 4 ? 4 : N_EDGES - base;
    int s[4], d[4];
    if (g_idx_is64) {
        const long long* ps = (const long long*)src_raw;
        const long long* pd = (const long long*)dst_raw;
        #pragma unroll
        for (int j = 0; j < 4; j++) {
            s[j] = (j < lim) ? (int)__ldg(&ps[base + j]) : -1;
            d[j] = (j < lim) ? (int)__ldg(&pd[base + j]) : -1;
        }
    } else {
        const int* ps = (const int*)src_raw;
        const int* pd = (const int*)dst_raw;
        #pragma unroll
        for (int j = 0; j < 4; j++) {
            s[j] = (j < lim) ? __ldg(&ps[base + j]) : -1;
            d[j] = (j < lim) ? __ldg(&pd[base + j]) : -1;
        }
    }
    #pragma unroll
    for (int j = 0; j < 4; j++) {
        if ((unsigned)s[j] < N_NODES && (unsigned)d[j] < N_NODES) {
            const int pos = atomicAdd(&g_cnt[d[j]], 1);
            if (pos < BIN_CAP)
                g_ssrc[(size_t)d[j] * BIN_CAP + pos] = s[j];
        }
    }
}

// ---------------------------------------------------------------------------
// W pre-convert: g_Whk[n][k] = half(W[k][n])
// ---------------------------------------------------------------------------
__global__ void wh_kernel(const float* __restrict__ W) {
    int i = blockIdx.x * blockDim.x + threadIdx.x;
    if (i >= IN_FEATS * OUT_FEATS) return;
    int n = i & (OUT_FEATS - 1);
    int k = i >> 7;
    g_Whk[(size_t)n * IN_FEATS + k] = __float2half(W[(size_t)k * OUT_FEATS + n]);
}

// ---------------------------------------------------------------------------
// GEMM: fp16 m16n8k16 mma.sync, fp32 accumulate — ROUND-14 PROVEN, frozen.
// ---------------------------------------------------------------------------
#define BK 32
#define ASTR 36
#define BSTRH 40
#define ABUF  (128 * ASTR)
#define BBUFH (128 * BSTRH)
#define SMEM_BYTES (2 * ABUF * 4 + 2 * BBUFH * 2)   // 57344

__device__ __forceinline__ void mma_fp16(float* d, const uint32_t* a,
                                         uint32_t b0, uint32_t b1) {
    asm volatile(
        "mma.sync.aligned.m16n8k16.row.col.f32.f16.f16.f32 "
        "{%0,%1,%2,%3}, {%4,%5,%6,%7}, {%8,%9}, {%0,%1,%2,%3};"
        : "+f"(d[0]), "+f"(d[1]), "+f"(d[2]), "+f"(d[3])
        : "r"(a[0]), "r"(a[1]), "r"(a[2]), "r"(a[3]), "r"(b0), "r"(b1));
}

__device__ __forceinline__ uint32_t pack_h2(float2 p) {
    __half2 h = __floats2half2_rn(p.x, p.y);
    return *reinterpret_cast<uint32_t*>(&h);
}

__device__ __forceinline__ void cp16(void* smem_dst, const void* gsrc) {
    uint32_t sa;
    asm("{ .reg .u64 t; cvta.to.shared.u64 t, %1; cvt.u32.u64 %0, t; }"
        : "=r"(sa) : "l"(smem_dst));
    asm volatile("cp.async.ca.shared.global [%0], [%1], 16;"
                 :: "r"(sa), "l"(gsrc) : "memory");
}

__global__ __launch_bounds__(256, 2)
void gemm_fp16_kernel(const float* __restrict__ feat) {
    extern __shared__ float smem[];
    float*  As = smem;                                        // [2][128][ASTR]
    __half* Bs = reinterpret_cast<__half*>(smem + 2 * ABUF);  // [2][128][BSTRH]

    const int tid  = threadIdx.x;
    const int lane = tid & 31;
    const int warp = tid >> 5;
    const int m0   = blockIdx.x * 128;

    const int wm = (warp >> 1) * 32;
    const int wn = (warp & 1) * 64;
    const int g  = lane >> 2;
    const int c  = lane & 3;

    float acc[2][8][4];
    #pragma unroll
    for (int i = 0; i < 2; i++)
        #pragma unroll
        for (int j = 0; j < 8; j++)
            #pragma unroll
            for (int q = 0; q < 4; q++) acc[i][j][q] = 0.f;

    #pragma unroll
    for (int p = 0; p < 4; p++) {
        const int ch = tid + 256 * p;
        int row = m0 + (ch >> 3);
        row = row < N_NODES ? row : N_NODES - 1;
        const int q = (ch & 7) * 4;
        cp16(&As[(ch >> 3) * ASTR + q], feat + (size_t)row * IN_FEATS + q);
    }
    #pragma unroll
    for (int p = 0; p < 2; p++) {
        const int ch = tid + 256 * p;
        const int n  = ch >> 2;
        const int ko = (ch & 3) * 8;
        cp16(&Bs[n * BSTRH + ko], g_Whk + (size_t)n * IN_FEATS + ko);
    }
    asm volatile("cp.async.commit_group;" ::: "memory");

    int buf = 0;
    for (int kt = 0; kt < IN_FEATS / BK; kt++) {
        if (kt + 1 < IN_FEATS / BK) {
            const int k0 = (kt + 1) * BK;
            float*  Ad = As + (buf ^ 1) * ABUF;
            __half* Bd = Bs + (buf ^ 1) * BBUFH;
            #pragma unroll
            for (int p = 0; p < 4; p++) {
                const int ch = tid + 256 * p;
                int row = m0 + (ch >> 3);
                row = row < N_NODES ? row : N_NODES - 1;
                const int q = (ch & 7) * 4;
                cp16(&Ad[(ch >> 3) * ASTR + q],
                     feat + (size_t)row * IN_FEATS + k0 + q);
            }
            #pragma unroll
            for (int p = 0; p < 2; p++) {
                const int ch = tid + 256 * p;
                const int n  = ch >> 2;
                const int ko = (ch & 3) * 8;
                cp16(&Bd[n * BSTRH + ko],
                     g_Whk + (size_t)n * IN_FEATS + k0 + ko);
            }
            asm volatile("cp.async.commit_group;" ::: "memory");
            asm volatile("cp.async.wait_group 1;" ::: "memory");
        } else {
            asm volatile("cp.async.wait_group 0;" ::: "memory");
        }
        __syncthreads();

        const float*  Ab = As + buf * ABUF;
        const __half* Bb = Bs + buf * BBUFH;

        #pragma unroll
        for (int s = 0; s < 2; s++) {
            const int kb = s * 16;
            uint32_t a[2][4];
            #pragma unroll
            for (int i = 0; i < 2; i++) {
                const int r = wm + i * 16 + g;
                a[i][0] = pack_h2(*reinterpret_cast<const float2*>(
                    &Ab[r * ASTR + kb + 2 * c]));
                a[i][1] = pack_h2(*reinterpret_cast<const float2*>(
                    &Ab[(r + 8) * ASTR + kb + 2 * c]));
                a[i][2] = pack_h2(*reinterpret_cast<const float2*>(
                    &Ab[r * ASTR + kb + 2 * c + 8]));
                a[i][3] = pack_h2(*reinterpret_cast<const float2*>(
                    &Ab[(r + 8) * ASTR + kb + 2 * c + 8]));
            }
            #pragma unroll
            for (int j = 0; j < 8; j++) {
                const int n = wn + j * 8 + g;
                const uint32_t b0 = *reinterpret_cast<const uint32_t*>(
                    &Bb[n * BSTRH + kb + 2 * c]);
                const uint32_t b1 = *reinterpret_cast<const uint32_t*>(
                    &Bb[n * BSTRH + kb + 2 * c + 8]);
                mma_fp16(acc[0][j], a[0], b0, b1);
                mma_fp16(acc[1][j], a[1], b0, b1);
            }
        }
        __syncthreads();
        buf ^= 1;
    }

    #pragma unroll
    for (int i = 0; i < 2; i++) {
        #pragma unroll
        for (int j = 0; j < 8; j++) {
            const int row0 = m0 + wm + i * 16 + g;
            const int col  = wn + j * 8 + 2 * c;
            if (row0 < N_NODES) {
                __half2 h = __floats2half2_rn(acc[i][j][0], acc[i][j][1]);
                *reinterpret_cast<__half2*>(
                    g_hself_h + (size_t)row0 * OUT_FEATS + col) = h;
            }
            const int row1 = row0 + 8;
            if (row1 < N_NODES) {
                __half2 h = __floats2half2_rn(acc[i][j][2], acc[i][j][3]);
                *reinterpret_cast<__half2*>(
                    g_hself_h + (size_t)row1 * OUT_FEATS + col) = h;
            }
        }
    }
}

// ---------------------------------------------------------------------------
// Aggregate + finalize: TWO nodes per warp. Half-warp (16 lanes) per node,
// each lane owns 8 halves (uint4 = 16 B). 8-row batches per half-warp give
// 16 outstanding row-gathers per warp. Predicated against each half's count.
// ---------------------------------------------------------------------------
__global__ __launch_bounds__(256)
void aggregate_kernel(float* __restrict__ out) {
    const int gw = (int)((blockIdx.x * (unsigned)blockDim.x + threadIdx.x) >> 5);
    const int lane = threadIdx.x & 31;
    const int half = lane >> 4;            // 0 or 1
    const int hl   = lane & 15;            // lane within half
    const int n    = gw * 2 + half;

    int cnt = 0;
    if (n < N_NODES) {
        cnt = g_cnt[n];
        cnt = cnt < BIN_CAP ? cnt : BIN_CAP;
    }
    const int beg = n * BIN_CAP;
    const int cnt_other = __shfl_xor_sync(0xffffffffu, cnt, 16);
    const int cntmax = cnt > cnt_other ? cnt : cnt_other;

    float acc[8];
    #pragma unroll
    for (int q = 0; q < 8; q++) acc[q] = 0.f;

    const uint4* hrow_base = reinterpret_cast<const uint4*>(g_hself_h);
    // row r begins at uint4 index r*16; lane's element is +hl

    for (int i = 0; i < cntmax; i += 8) {
        int sv[8];
        #pragma unroll
        for (int q = 0; q < 8; q++)
            sv[q] = (i + q < cnt) ? __ldg(&g_ssrc[beg + i + q]) : -1;
        uint4 u[8];
        #pragma unroll
        for (int q = 0; q < 8; q++)
            u[q] = (sv[q] >= 0)
                 ? __ldg(hrow_base + (size_t)sv[q] * 16 + hl)
                 : make_uint4(0u, 0u, 0u, 0u);
        #pragma unroll
        for (int q = 0; q < 8; q++) {
            const float2 f0 = __half22float2(*reinterpret_cast<const __half2*>(&u[q].x));
            const float2 f1 = __half22float2(*reinterpret_cast<const __half2*>(&u[q].y));
            const float2 f2 = __half22float2(*reinterpret_cast<const __half2*>(&u[q].z));
            const float2 f3 = __half22float2(*reinterpret_cast<const __half2*>(&u[q].w));
            acc[0] += f0.x; acc[1] += f0.y; acc[2] += f1.x; acc[3] += f1.y;
            acc[4] += f2.x; acc[5] += f2.y; acc[6] += f3.x; acc[7] += f3.y;
        }
    }

    if (n >= N_NODES) return;

    const uint4 us = __ldg(hrow_base + (size_t)n * 16 + hl);
    const float2 s0 = __half22float2(*reinterpret_cast<const __half2*>(&us.x));
    const float2 s1 = __half22float2(*reinterpret_cast<const __half2*>(&us.y));
    const float2 s2 = __half22float2(*reinterpret_cast<const __half2*>(&us.z));
    const float2 s3 = __half22float2(*reinterpret_cast<const __half2*>(&us.w));

    const float invd = 1.0f / ((float)cnt + 1.0f);

    float4 r0, r1;
    r0.x = fmaxf((acc[0] + s0.x) * invd, 0.f);
    r0.y = fmaxf((acc[1] + s0.y) * invd, 0.f);
    r0.z = fmaxf((acc[2] + s1.x) * invd, 0.f);
    r0.w = fmaxf((acc[3] + s1.y) * invd, 0.f);
    r1.x = fmaxf((acc[4] + s2.x) * invd, 0.f);
    r1.y = fmaxf((acc[5] + s2.y) * invd, 0.f);
    r1.z = fmaxf((acc[6] + s3.x) * invd, 0.f);
    r1.w = fmaxf((acc[7] + s3.y) * invd, 0.f);

    float* orow = out + (size_t)n * OUT_FEATS + hl * 8;
    *reinterpret_cast<float4*>(orow + 0) = r0;
    *reinterpret_cast<float4*>(orow + 4) = r1;
}

// ---------------------------------------------------------------------------
// kernel_launch:
//   side: wh -> [ev whdone] -> detect+zero -> bin -> [ev csr]
//   main: [wait whdone] gemm -> [wait csr] aggregate
// ---------------------------------------------------------------------------
extern "C" void kernel_launch(void* const* d_in, const int* in_sizes, int n_in,
                              void* d_out, int out_size) {
    const float* feat = (const float*)d_in[0];
    const float* W    = (const float*)d_in[1];
    const void*  src  = d_in[2];
    const void*  dst  = d_in[3];
    float*       out  = (float*)d_out;

    cudaFuncSetAttribute(gemm_fp16_kernel,
                         cudaFuncAttributeMaxDynamicSharedMemorySize, SMEM_BYTES);

    const int gemm_blocks = (N_NODES + 127) / 128;          // 782
    const int agg_warps   = (N_NODES + 1) / 2;              // 2 nodes per warp
    const int agg_blocks  = (int)(((long long)agg_warps * 32 + 255) / 256);
    const int dz_blocks   = 1 + (N_NODES + 255) / 256;

    if (g_sh.ok) {
        cudaEventRecord(g_sh.fork, 0);
        cudaStreamWaitEvent(g_sh.s, g_sh.fork, 0);

        // side stream: wh first (frees main to start gemm ASAP), then binning
        wh_kernel<<<(IN_FEATS * OUT_FEATS + 255) / 256, 256, 0, g_sh.s>>>(W);
        cudaEventRecord(g_sh.whdone, g_sh.s);
        detect_zero_kernel<<<dz_blocks, 256, 0, g_sh.s>>>(dst, in_sizes[3]);
        bin_kernel<<<(N_EDGES / 4 + 255) / 256, 256, 0, g_sh.s>>>(src, dst);
        cudaEventRecord(g_sh.csr, g_sh.s);

        // main stream: gemm (after W is converted), then aggregate after join
        cudaStreamWaitEvent(0, g_sh.whdone, 0);
        gemm_fp16_kernel<<<gemm_blocks, 256, SMEM_BYTES>>>(feat);
        cudaStreamWaitEvent(0, g_sh.csr, 0);
        aggregate_kernel<<<agg_blocks, 256>>>(out);
    } else {
        wh_kernel<<<(IN_FEATS * OUT_FEATS + 255) / 256, 256>>>(W);
        detect_zero_kernel<<<dz_blocks, 256>>>(dst, in_sizes[3]);
        gemm_fp16_kernel<<<gemm_blocks, 256, SMEM_BYTES>>>(feat);
        bin_kernel<<<(N_EDGES / 4 + 255) / 256, 256>>>(src, dst);
        aggregate_kernel<<<agg_blocks, 256>>>(out);
    }
}